// round 1
// baseline (speedup 1.0000x reference)
#include <cuda_runtime.h>
#include <cstdint>

#define MAXP 150016
#define NC   80
#define TOPK 13
#define EPSV 1e-9f

// Scratch (allocation-free rule: __device__ globals)
__device__ float g_clsT[(size_t)NC * MAXP];   // transposed class scores [class][prior]
__device__ int   g_count[MAXP];               // # of GTs marking this prior in their top-13
__device__ int   g_firstg[MAXP];              // min g marking this prior

__device__ __forceinline__ bool better(float v1, int i1, float v2, int i2) {
    // total order: value descending, index ascending (matches lax.top_k tie rule)
    return (v1 > v2) || (v1 == v2 && i1 < i2);
}

// ---------------------------------------------------------------------------
// Kernel 0: init scratch
// ---------------------------------------------------------------------------
__global__ void init_kernel(int Pp) {
    int p = blockIdx.x * blockDim.x + threadIdx.x;
    if (p < Pp) { g_count[p] = 0; g_firstg[p] = 0x7FFFFFFF; }
}

// ---------------------------------------------------------------------------
// Kernel 1: transpose cls_pred [P][80] -> g_clsT [80][P]
// ---------------------------------------------------------------------------
__global__ __launch_bounds__(256) void transpose_kernel(const float* __restrict__ cls, int Pp) {
    __shared__ float tile[32][NC + 1];
    int p0 = blockIdx.x * 32;
    int t = threadIdx.x;
    for (int i = t; i < 32 * NC; i += 256) {
        int pl = i / NC, c = i - pl * NC;
        int p = p0 + pl;
        tile[pl][c] = (p < Pp) ? cls[(size_t)p * NC + c] : 0.f;
    }
    __syncthreads();
    for (int i = t; i < NC * 32; i += 256) {
        int c = i >> 5, pl = i & 31;
        int p = p0 + pl;
        if (p < Pp) g_clsT[(size_t)c * MAXP + p] = tile[pl][c];
    }
}

// ---------------------------------------------------------------------------
// Kernel 2: per-GT top-13 of alignment metric; mark count/firstg
// one block per GT, 256 threads
// ---------------------------------------------------------------------------
__global__ __launch_bounds__(256) void topk_kernel(const float* __restrict__ bbox_pred,
                                                   const float* __restrict__ bbox_gt,
                                                   const int* __restrict__ label_gt,
                                                   int Pp) {
    int g = blockIdx.x;
    int t = threadIdx.x;
    const float4 gb = ((const float4*)bbox_gt)[g];
    int cls = label_gt[g] - 1;
    const float* __restrict__ srow = g_clsT + (size_t)cls * MAXP;
    const float garea = fmaxf(gb.z - gb.x, 0.f) * fmaxf(gb.w - gb.y, 0.f);

    float val[TOPK]; int idx[TOPK];
    #pragma unroll
    for (int j = 0; j < TOPK; j++) { val[j] = -1.f; idx[j] = 0x7FFFFFFF; }

    const float4* __restrict__ bp = (const float4*)bbox_pred;
    for (int p = t; p < Pp; p += 256) {
        float4 b = bp[p];
        float iw = fminf(gb.z, b.z) - fmaxf(gb.x, b.x);
        float ih = fminf(gb.w, b.w) - fmaxf(gb.y, b.y);
        float inter = fmaxf(iw, 0.f) * fmaxf(ih, 0.f);
        float parea = fmaxf(b.z - b.x, 0.f) * fmaxf(b.w - b.y, 0.f);
        float iou = inter / (garea + parea - inter + EPSV);
        float i2 = iou * iou;
        float m = srow[p] * (i2 * i2 * i2);   // score^1 * iou^6
        if (better(m, p, val[TOPK - 1], idx[TOPK - 1])) {
            float cv = m; int ci = p;
            #pragma unroll
            for (int j = 0; j < TOPK; j++) {
                if (better(cv, ci, val[j], idx[j])) {
                    float tv = val[j]; int ti = idx[j];
                    val[j] = cv; idx[j] = ci; cv = tv; ci = ti;
                }
            }
        }
    }

    // block merge: 256 sorted lists of 13 -> global top-13
    __shared__ float sval[256 * TOPK];
    __shared__ int   sidx[256 * TOPK];
    #pragma unroll
    for (int j = 0; j < TOPK; j++) { sval[t * TOPK + j] = val[j]; sidx[t * TOPK + j] = idx[j]; }

    __shared__ float wv[8]; __shared__ int wi[8]; __shared__ int ws[8];
    __shared__ float selv[TOPK]; __shared__ int seli[TOPK];
    __shared__ int winner;
    int ptr = 0;
    __syncthreads();

    for (int r = 0; r < TOPK; r++) {
        float cv = (ptr < TOPK) ? sval[t * TOPK + ptr] : -2.f;
        int   ci = (ptr < TOPK) ? sidx[t * TOPK + ptr] : 0x7FFFFFFF;
        int   cs = t;
        #pragma unroll
        for (int o = 16; o > 0; o >>= 1) {
            float ov = __shfl_down_sync(0xffffffffu, cv, o);
            int   oi = __shfl_down_sync(0xffffffffu, ci, o);
            int   os = __shfl_down_sync(0xffffffffu, cs, o);
            if (better(ov, oi, cv, ci)) { cv = ov; ci = oi; cs = os; }
        }
        if ((t & 31) == 0) { wv[t >> 5] = cv; wi[t >> 5] = ci; ws[t >> 5] = cs; }
        __syncthreads();
        if (t < 32) {
            cv = (t < 8) ? wv[t] : -3.f;
            ci = (t < 8) ? wi[t] : 0x7FFFFFFF;
            cs = (t < 8) ? ws[t] : -1;
            #pragma unroll
            for (int o = 4; o > 0; o >>= 1) {
                float ov = __shfl_down_sync(0xffffffffu, cv, o);
                int   oi = __shfl_down_sync(0xffffffffu, ci, o);
                int   os = __shfl_down_sync(0xffffffffu, cs, o);
                if (better(ov, oi, cv, ci)) { cv = ov; ci = oi; cs = os; }
            }
            if (t == 0) { selv[r] = cv; seli[r] = ci; winner = cs; }
        }
        __syncthreads();
        if (t == winner) ptr++;
        __syncthreads();
    }

    // keep-gate: if row max <= eps, reference zeroes all marks
    if (t < TOPK && selv[0] > EPSV) {
        atomicAdd(&g_count[seli[t]], 1);
        atomicMin(&g_firstg[seli[t]], g);
    }
}

// ---------------------------------------------------------------------------
// Kernel 3: per-prior resolution + all outputs
// out layout (float32): [P gt_index][P labels][P*80 one-hot][P*4 bboxes]
// ---------------------------------------------------------------------------
__global__ __launch_bounds__(256) void finalize_kernel(const float* __restrict__ bbox_pred,
                                                       const float* __restrict__ bbox_gt,
                                                       const int* __restrict__ label_gt,
                                                       float* __restrict__ out,
                                                       int Pp, int Ngt) {
    __shared__ float4 gbox[256];
    __shared__ int    glbl[256];
    __shared__ int    s_cidx[256];
    int t = threadIdx.x;
    if (t < Ngt) { gbox[t] = ((const float4*)bbox_gt)[t]; glbl[t] = label_gt[t]; }
    __syncthreads();

    int p = blockIdx.x * 256 + t;
    int assigned = 0, lblout = 0;
    if (p < Pp) {
        float4 b = ((const float4*)bbox_pred)[p];
        float parea = fmaxf(b.z - b.x, 0.f) * fmaxf(b.w - b.y, 0.f);
        float best = -1.f; int bg = 0;
        for (int g = 0; g < Ngt; g++) {
            float4 gb = gbox[g];
            float iw = fminf(gb.z, b.z) - fmaxf(gb.x, b.x);
            float ih = fminf(gb.w, b.w) - fmaxf(gb.y, b.y);
            float inter = fmaxf(iw, 0.f) * fmaxf(ih, 0.f);
            float garea = fmaxf(gb.z - gb.x, 0.f) * fmaxf(gb.w - gb.y, 0.f);
            float iou = inter / (garea + parea - inter + EPSV);
            if (iou > best) { best = iou; bg = g; }   // first max wins (argmax semantics)
        }
        int cnt = g_count[p];
        int fg  = g_firstg[p];
        assigned = (cnt == 0) ? 0 : ((cnt == 1) ? fg : bg);
        lblout   = (cnt > 0) ? glbl[assigned] : 0;
    }
    s_cidx[t] = (p < Pp) ? (glbl[assigned] - 1) : -1;  // one-hot class (unconditional per reference)
    __syncthreads();

    size_t o1 = (size_t)Pp;
    size_t o2 = (size_t)2 * Pp;
    size_t o3 = (size_t)2 * Pp + (size_t)NC * Pp;

    if (p < Pp) {
        out[p]      = (float)assigned;
        out[o1 + p] = (float)lblout;
        ((float4*)(out + o3))[p] = gbox[assigned];
    }
    // coalesced cooperative one-hot write for this block's 256 priors
    int pbase = blockIdx.x * 256;
    for (int e = t; e < 256 * NC; e += 256) {
        int pl = e / NC, c = e - pl * NC;
        int pp = pbase + pl;
        if (pp < Pp) out[o2 + (size_t)pp * NC + c] = (c == s_cidx[pl]) ? 1.f : 0.f;
    }
}

// ---------------------------------------------------------------------------
extern "C" void kernel_launch(void* const* d_in, const int* in_sizes, int n_in,
                              void* d_out, int out_size) {
    const float* cls_pred  = (const float*)d_in[0];
    const float* bbox_pred = (const float*)d_in[1];
    const int*   label_gt  = (const int*)d_in[2];
    const float* bbox_gt   = (const float*)d_in[3];
    float* out = (float*)d_out;

    int Pp  = in_sizes[1] / 4;   // 150000
    int Ngt = in_sizes[2];       // 256

    init_kernel<<<(Pp + 255) / 256, 256>>>(Pp);
    transpose_kernel<<<(Pp + 31) / 32, 256>>>(cls_pred, Pp);
    topk_kernel<<<Ngt, 256>>>(bbox_pred, bbox_gt, label_gt, Pp);
    finalize_kernel<<<(Pp + 255) / 256, 256>>>(bbox_pred, bbox_gt, label_gt, out, Pp, Ngt);
}

// round 3
// speedup vs baseline: 1.3543x; 1.3543x over previous
#include <cuda_runtime.h>
#include <cstdint>

#define MAXP   150016
#define NC     80
#define TOPK   13
#define EPSV   1e-9f
#define NSPLIT 32
#define TILE   512
#define MAXG   256

// Scratch (__device__ globals; no allocation allowed)
__device__ float g_clsT[(size_t)NC * MAXP];        // transposed scores [class][prior]
__device__ int   g_count[MAXP];                    // # GTs marking prior in top-13
__device__ int   g_firstg[MAXP];                   // min marking g; overwritten by resolve for count>1
__device__ float g_pval[(size_t)MAXG * NSPLIT * TOPK];
__device__ int   g_pidx[(size_t)MAXG * NSPLIT * TOPK];
__device__ int   g_list[MAXG * TOPK / 2 + 8];      // priors with count>1
__device__ int   g_nlist;

__device__ __forceinline__ bool better(float v1, int i1, float v2, int i2) {
    // total order: value desc, index asc (lax.top_k / first-max-wins tie rule)
    return (v1 > v2) || (v1 == v2 && i1 < i2);
}

// ---------------------------------------------------------------------------
// Kernel 1: transpose cls_pred [P][80] -> g_clsT [80][P]; also init scratch
// ---------------------------------------------------------------------------
__global__ __launch_bounds__(256) void transpose_init_kernel(const float* __restrict__ cls, int Pp) {
    __shared__ float tile[32][NC + 1];
    int p0 = blockIdx.x * 32;
    int t = threadIdx.x;
    if (blockIdx.x == 0 && t == 0) g_nlist = 0;
    if (t < 32) {
        int p = p0 + t;
        if (p < Pp) { g_count[p] = 0; g_firstg[p] = 0x7FFFFFFF; }
    }
    for (int i = t; i < 32 * NC; i += 256) {
        int pl = i / NC, c = i - pl * NC;
        int p = p0 + pl;
        tile[pl][c] = (p < Pp) ? cls[(size_t)p * NC + c] : 0.f;
    }
    __syncthreads();
    for (int i = t; i < NC * 32; i += 256) {
        int c = i >> 5, pl = i & 31;
        int p = p0 + pl;
        if (p < Pp) g_clsT[(size_t)c * MAXP + p] = tile[pl][c];
    }
}

// ---------------------------------------------------------------------------
// Kernel 2: partial top-13. Block = (split s, GT-group of 8). One warp per GT.
// bbox tile staged in shared once per block, reused by all 8 warps/GTs.
// ---------------------------------------------------------------------------
__global__ __launch_bounds__(256) void topk_partial_kernel(const float* __restrict__ bbox_pred,
                                                           const float* __restrict__ bbox_gt,
                                                           const int* __restrict__ label_gt,
                                                           int Pp, int Ngt) {
    __shared__ float4 btile[TILE];
    __shared__ float  sval[256 * TOPK];
    __shared__ int    sidx[256 * TOPK];

    int grp = blockIdx.x & 31;         // GT group
    int s   = blockIdx.x >> 5;         // split
    int t = threadIdx.x;
    int w = t >> 5, lane = t & 31;
    int g = grp * 8 + w;
    int gc = (g < Ngt) ? g : 0;        // clamp; inactive warps still do staging

    const float4 gb = ((const float4*)bbox_gt)[gc];
    int cls = label_gt[gc] - 1;
    const float* __restrict__ srow = g_clsT + (size_t)cls * MAXP;
    const float garea = fmaxf(gb.z - gb.x, 0.f) * fmaxf(gb.w - gb.y, 0.f);

    int chunk = (Pp + NSPLIT - 1) / NSPLIT;
    int lo = s * chunk;
    int hi = min(lo + chunk, Pp);

    float val[TOPK]; int idx[TOPK];
    #pragma unroll
    for (int j = 0; j < TOPK; j++) { val[j] = -1.f; idx[j] = 0x7FFFFFFF; }

    const float4* __restrict__ bp = (const float4*)bbox_pred;
    for (int base = lo; base < hi; base += TILE) {
        int n = min(TILE, hi - base);
        __syncthreads();
        for (int j = t; j < n; j += 256) btile[j] = bp[base + j];
        __syncthreads();
        for (int j = lane; j < n; j += 32) {
            int p = base + j;
            float4 b = btile[j];
            float iw = fminf(gb.z, b.z) - fmaxf(gb.x, b.x);
            float ih = fminf(gb.w, b.w) - fmaxf(gb.y, b.y);
            float inter = fmaxf(iw, 0.f) * fmaxf(ih, 0.f);
            float parea = fmaxf(b.z - b.x, 0.f) * fmaxf(b.w - b.y, 0.f);
            float iou = inter / (garea + parea - inter + EPSV);
            float i2 = iou * iou;
            float m = srow[p] * (i2 * i2 * i2);     // score^1 * iou^6
            if (better(m, p, val[TOPK - 1], idx[TOPK - 1])) {
                float cv = m; int ci = p;
                #pragma unroll
                for (int j2 = 0; j2 < TOPK; j2++) {
                    if (better(cv, ci, val[j2], idx[j2])) {
                        float tv = val[j2]; int ti = idx[j2];
                        val[j2] = cv; idx[j2] = ci; cv = tv; ci = ti;
                    }
                }
            }
        }
    }

    // per-warp tournament: 32 sorted 13-lists -> warp top-13 (via shared, dynamic ptr)
    #pragma unroll
    for (int j = 0; j < TOPK; j++) { sval[t * TOPK + j] = val[j]; sidx[t * TOPK + j] = idx[j]; }
    __syncwarp();

    int ptr = 0;
    float outv = -1.f; int outi = 0x7FFFFFFF;
    for (int r = 0; r < TOPK; r++) {
        float cv = (ptr < TOPK) ? sval[t * TOPK + ptr] : -2.f;
        int   ci = (ptr < TOPK) ? sidx[t * TOPK + ptr] : 0x7FFFFFFF;
        int   cs = lane;
        #pragma unroll
        for (int o = 16; o > 0; o >>= 1) {
            float ov = __shfl_xor_sync(0xffffffffu, cv, o);
            int   oi = __shfl_xor_sync(0xffffffffu, ci, o);
            int   os = __shfl_xor_sync(0xffffffffu, cs, o);
            if (better(ov, oi, cv, ci)) { cv = ov; ci = oi; cs = os; }
        }
        if (lane == r)  { outv = cv; outi = ci; }
        if (lane == cs) ptr++;
    }
    if (g < Ngt && lane < TOPK) {
        size_t off = ((size_t)g * NSPLIT + s) * TOPK + lane;
        g_pval[off] = outv; g_pidx[off] = outi;
    }
}

// ---------------------------------------------------------------------------
// Kernel 3: merge 32 partial lists per GT -> global top-13, mark count/firstg
// ---------------------------------------------------------------------------
__global__ __launch_bounds__(512) void topk_merge_kernel() {
    int g = blockIdx.x;
    int t = threadIdx.x;
    int w = t >> 5, lane = t & 31;
    const int NCAND = NSPLIT * TOPK;   // 416

    float cv = -2.f; int ci = 0x7FFFFFFF;
    if (t < NCAND) {
        cv = g_pval[(size_t)g * NCAND + t];
        ci = g_pidx[(size_t)g * NCAND + t];
    }

    __shared__ float sv[16]; __shared__ int si[16]; __shared__ int ss[16];
    __shared__ float selv0; __shared__ int seli[TOPK]; __shared__ int winner;

    for (int r = 0; r < TOPK; r++) {
        __syncthreads();
        float v = cv; int i = ci; int src = t;
        #pragma unroll
        for (int o = 16; o > 0; o >>= 1) {
            float ov = __shfl_xor_sync(0xffffffffu, v, o);
            int   oi = __shfl_xor_sync(0xffffffffu, i, o);
            int   os = __shfl_xor_sync(0xffffffffu, src, o);
            if (better(ov, oi, v, i)) { v = ov; i = oi; src = os; }
        }
        if (lane == 0) { sv[w] = v; si[w] = i; ss[w] = src; }
        __syncthreads();
        if (t < 32) {
            v = (t < 16) ? sv[t] : -3.f;
            i = (t < 16) ? si[t] : 0x7FFFFFFF;
            src = (t < 16) ? ss[t] : -1;
            #pragma unroll
            for (int o = 8; o > 0; o >>= 1) {
                float ov = __shfl_xor_sync(0xffffffffu, v, o);
                int   oi = __shfl_xor_sync(0xffffffffu, i, o);
                int   os = __shfl_xor_sync(0xffffffffu, src, o);
                if (better(ov, oi, v, i)) { v = ov; i = oi; src = os; }
            }
            if (t == 0) { if (r == 0) selv0 = v; seli[r] = i; winner = src; }
        }
        __syncthreads();
        if (t == winner) cv = -2.f;
    }
    __syncthreads();
    // keep-gate: if row max <= eps, reference drops all marks of this GT
    if (t < TOPK && selv0 > EPSV) {
        atomicAdd(&g_count[seli[t]], 1);
        atomicMin(&g_firstg[seli[t]], g);
    }
}

// ---------------------------------------------------------------------------
// Kernel 4: collect priors with count > 1 (at most Ngt*13/2)
// ---------------------------------------------------------------------------
__global__ __launch_bounds__(256) void collect_kernel(int Pp) {
    int p = blockIdx.x * 256 + threadIdx.x;
    if (p < Pp && g_count[p] > 1) {
        int k = atomicAdd(&g_nlist, 1);
        g_list[k] = p;
    }
}

// ---------------------------------------------------------------------------
// Kernel 5: for each contested prior, IoU-argmax over GTs (first max wins);
// overwrite g_firstg[p] with the winner.
// ---------------------------------------------------------------------------
__global__ __launch_bounds__(256) void resolve_kernel(const float* __restrict__ bbox_pred,
                                                      const float* __restrict__ bbox_gt,
                                                      int Ngt) {
    if ((int)blockIdx.x >= g_nlist) return;
    int p = g_list[blockIdx.x];
    int t = threadIdx.x;
    int w = t >> 5, lane = t & 31;

    float4 b = ((const float4*)bbox_pred)[p];
    float parea = fmaxf(b.z - b.x, 0.f) * fmaxf(b.w - b.y, 0.f);

    float cv = -1.f; int ci = t;
    if (t < Ngt) {
        float4 gb = ((const float4*)bbox_gt)[t];
        float iw = fminf(gb.z, b.z) - fmaxf(gb.x, b.x);
        float ih = fminf(gb.w, b.w) - fmaxf(gb.y, b.y);
        float inter = fmaxf(iw, 0.f) * fmaxf(ih, 0.f);
        float garea = fmaxf(gb.z - gb.x, 0.f) * fmaxf(gb.w - gb.y, 0.f);
        cv = inter / (garea + parea - inter + EPSV);
    }
    __shared__ float sv[8]; __shared__ int si[8];
    #pragma unroll
    for (int o = 16; o > 0; o >>= 1) {
        float ov = __shfl_xor_sync(0xffffffffu, cv, o);
        int   oi = __shfl_xor_sync(0xffffffffu, ci, o);
        if (better(ov, oi, cv, ci)) { cv = ov; ci = oi; }
    }
    if (lane == 0) { sv[w] = cv; si[w] = ci; }
    __syncthreads();
    if (t < 8) {
        cv = sv[t]; ci = si[t];
        #pragma unroll
        for (int o = 4; o > 0; o >>= 1) {
            float ov = __shfl_xor_sync(0xffu, cv, o);
            int   oi = __shfl_xor_sync(0xffu, ci, o);
            if (better(ov, oi, cv, ci)) { cv = ov; ci = oi; }
        }
        if (t == 0) g_firstg[p] = ci;
    }
}

// ---------------------------------------------------------------------------
// Kernel 6: outputs. layout: [P gt_index][P labels][P*80 one-hot][P*4 bboxes]
// No IoU work here — assignment is fully resolved in g_count/g_firstg.
// ---------------------------------------------------------------------------
__global__ __launch_bounds__(256) void finalize_kernel(const float* __restrict__ bbox_gt,
                                                       const int* __restrict__ label_gt,
                                                       float* __restrict__ out,
                                                       int Pp, int Ngt) {
    __shared__ float4 gbox[MAXG];
    __shared__ int    glbl[MAXG];
    __shared__ int    s_cidx[256];
    int t = threadIdx.x;
    if (t < Ngt) { gbox[t] = ((const float4*)bbox_gt)[t]; glbl[t] = label_gt[t]; }
    __syncthreads();

    int pbase = blockIdx.x * 256;
    int p = pbase + t;
    int assigned = 0, lblout = 0;
    if (p < Pp) {
        int cnt = g_count[p];
        assigned = (cnt > 0) ? g_firstg[p] : 0;   // cnt>1 already resolved to argmax
        lblout   = (cnt > 0) ? glbl[assigned] : 0;
    }
    s_cidx[t] = (p < Pp) ? (glbl[assigned] - 1) : -1;
    __syncthreads();

    size_t o1 = (size_t)Pp;
    size_t o2 = (size_t)2 * Pp;
    size_t o3 = (size_t)2 * Pp + (size_t)NC * Pp;

    if (p < Pp) {
        out[p]      = (float)assigned;
        out[o1 + p] = (float)lblout;
        ((float4*)(out + o3))[p] = gbox[assigned];
    }
    // one-hot: contiguous float4 stores for this block's 256*80 floats
    float4* o2v = (float4*)(out + o2 + (size_t)pbase * NC);
    for (int e = t; e < 256 * NC / 4; e += 256) {
        int pl = e / (NC / 4);
        if (pbase + pl >= Pp) break;
        int c0 = (e - pl * (NC / 4)) * 4;
        int ci = s_cidx[pl];
        float4 v;
        v.x = (c0 + 0 == ci) ? 1.f : 0.f;
        v.y = (c0 + 1 == ci) ? 1.f : 0.f;
        v.z = (c0 + 2 == ci) ? 1.f : 0.f;
        v.w = (c0 + 3 == ci) ? 1.f : 0.f;
        o2v[e] = v;
    }
}

// ---------------------------------------------------------------------------
extern "C" void kernel_launch(void* const* d_in, const int* in_sizes, int n_in,
                              void* d_out, int out_size) {
    const float* cls_pred  = (const float*)d_in[0];
    const float* bbox_pred = (const float*)d_in[1];
    const int*   label_gt  = (const int*)d_in[2];
    const float* bbox_gt   = (const float*)d_in[3];
    float* out = (float*)d_out;

    int Pp  = in_sizes[1] / 4;   // 150000
    int Ngt = in_sizes[2];       // 256
    int ngrp = (Ngt + 7) / 8;

    transpose_init_kernel<<<(Pp + 31) / 32, 256>>>(cls_pred, Pp);
    topk_partial_kernel<<<NSPLIT * ngrp, 256>>>(bbox_pred, bbox_gt, label_gt, Pp, Ngt);
    topk_merge_kernel<<<Ngt, 512>>>();
    collect_kernel<<<(Pp + 255) / 256, 256>>>(Pp);
    resolve_kernel<<<Ngt * TOPK / 2 + 1, 256>>>(bbox_pred, bbox_gt, Ngt);
    finalize_kernel<<<(Pp + 255) / 256, 256>>>(bbox_gt, label_gt, out, Pp, Ngt);
}

// round 5
// speedup vs baseline: 1.7111x; 1.2635x over previous
#include <cuda_runtime.h>
#include <cstdint>

#define MAXP   150016
#define NC     80
#define TOPK   13
#define EPSV   1e-9f
#define NSPLIT 16
#define TILE   1024
#define MAXG   256
#define TPB    128      // threads per topk block (4 GTs, 1 warp each)

// Scratch (__device__ globals; no allocation allowed)
__device__ float g_clsT[(size_t)NC * MAXP];            // transposed scores [class][prior]
__device__ int   g_count[MAXP];
__device__ int   g_firstg[MAXP];
__device__ float g_pval[(size_t)MAXG * NSPLIT * TOPK];
__device__ int   g_pidx[(size_t)MAXG * NSPLIT * TOPK];
__device__ int   g_list[MAXG * TOPK / 2 + 8];
__device__ int   g_nlist;

__device__ __forceinline__ bool better(float v1, int i1, float v2, int i2) {
    // total order: value desc, index asc (lax.top_k / first-max-wins tie rule)
    return (v1 > v2) || (v1 == v2 && i1 < i2);
}

// ---------------------------------------------------------------------------
// Kernel 1: transpose cls_pred [P][80] -> g_clsT [80][P]; init scratch
// ---------------------------------------------------------------------------
__global__ __launch_bounds__(256) void transpose_init_kernel(const float* __restrict__ cls, int Pp) {
    __shared__ float tile[32][NC + 1];
    int p0 = blockIdx.x * 32;
    int t = threadIdx.x;
    if (blockIdx.x == 0 && t == 0) g_nlist = 0;
    if (t < 32) {
        int p = p0 + t;
        if (p < Pp) { g_count[p] = 0; g_firstg[p] = 0x7FFFFFFF; }
    }
    for (int i = t; i < 32 * NC; i += 256) {
        int pl = i / NC, c = i - pl * NC;
        int p = p0 + pl;
        tile[pl][c] = (p < Pp) ? cls[(size_t)p * NC + c] : 0.f;
    }
    __syncthreads();
    for (int i = t; i < NC * 32; i += 256) {
        int c = i >> 5, pl = i & 31;
        int p = p0 + pl;
        if (p < Pp) g_clsT[(size_t)c * MAXP + p] = tile[pl][c];
    }
}

// ---------------------------------------------------------------------------
// Kernel 2: partial top-13. Block = (split s, GT-group of 4). One warp per GT.
// Per-thread top-13 lists live in plane-major shared; only the 13th value
// (threshold) stays in a register, so the hot loop is one compare.
// ---------------------------------------------------------------------------
__global__ __launch_bounds__(TPB) void topk_partial_kernel(const float* __restrict__ bbox_pred,
                                                           const float* __restrict__ bbox_gt,
                                                           const int* __restrict__ label_gt,
                                                           int Pp, int Ngt, int ngrp) {
    __shared__ float4 btile[TILE];
    __shared__ float  sval[TOPK * TPB];   // [j][t] plane-major: conflict-free
    __shared__ int    sidx[TOPK * TPB];

    int grp = blockIdx.x % ngrp;
    int s   = blockIdx.x / ngrp;
    int t = threadIdx.x;
    int w = t >> 5, lane = t & 31;
    int g = grp * 4 + w;
    int gc = (g < Ngt) ? g : 0;

    const float4 gb = ((const float4*)bbox_gt)[gc];
    int cls = label_gt[gc] - 1;
    const float* __restrict__ srow = g_clsT + (size_t)cls * MAXP;
    const float garea = fmaxf(gb.z - gb.x, 0.f) * fmaxf(gb.w - gb.y, 0.f);

    int chunk = (Pp + NSPLIT - 1) / NSPLIT;
    int lo = s * chunk;
    int hi = min(lo + chunk, Pp);

    #pragma unroll
    for (int j = 0; j < TOPK; j++) { sval[j * TPB + t] = -1.f; sidx[j * TPB + t] = 0x7FFFFFFF; }
    float thr = -1.f;

    const float4* __restrict__ bp = (const float4*)bbox_pred;
    for (int base = lo; base < hi; base += TILE) {
        int n = min(TILE, hi - base);
        __syncthreads();
        for (int i = t; i < n; i += TPB) btile[i] = bp[base + i];
        __syncthreads();
        for (int j = lane; j < n; j += 32) {
            int p = base + j;
            float4 b = btile[j];
            float iw = fminf(gb.z, b.z) - fmaxf(gb.x, b.x);
            float ih = fminf(gb.w, b.w) - fmaxf(gb.y, b.y);
            float inter = fmaxf(iw, 0.f) * fmaxf(ih, 0.f);
            float parea = fmaxf(b.z - b.x, 0.f) * fmaxf(b.w - b.y, 0.f);
            float iou = inter / (garea + parea - inter + EPSV);
            float i2 = iou * iou;
            float m = srow[p] * (i2 * i2 * i2);    // score^1 * iou^6
            // Within a lane p strictly increases, so equality must NOT insert
            // (existing entry has the smaller index) -> single compare suffices.
            if (m > thr) {
                int pos = TOPK - 1;
                #pragma unroll
                for (int q = TOPK - 1; q > 0; q--) {
                    if (pos == q && better(m, p, sval[(q - 1) * TPB + t], sidx[(q - 1) * TPB + t])) {
                        sval[q * TPB + t] = sval[(q - 1) * TPB + t];
                        sidx[q * TPB + t] = sidx[(q - 1) * TPB + t];
                        pos = q - 1;
                    }
                }
                sval[pos * TPB + t] = m; sidx[pos * TPB + t] = p;
                thr = sval[(TOPK - 1) * TPB + t];
            }
        }
    }
    __syncwarp();

    // warp tournament: 32 sorted 13-lists -> warp top-13
    int ptr = 0;
    float outv = -1.f; int outi = 0x7FFFFFFF;
    for (int r = 0; r < TOPK; r++) {
        float cv = (ptr < TOPK) ? sval[ptr * TPB + t] : -2.f;
        int   ci = (ptr < TOPK) ? sidx[ptr * TPB + t] : 0x7FFFFFFF;
        int   cs = lane;
        #pragma unroll
        for (int o = 16; o > 0; o >>= 1) {
            float ov = __shfl_xor_sync(0xffffffffu, cv, o);
            int   oi = __shfl_xor_sync(0xffffffffu, ci, o);
            int   os = __shfl_xor_sync(0xffffffffu, cs, o);
            if (better(ov, oi, cv, ci)) { cv = ov; ci = oi; cs = os; }
        }
        if (lane == r)  { outv = cv; outi = ci; }
        if (lane == cs) ptr++;
    }
    if (g < Ngt && lane < TOPK) {
        size_t off = ((size_t)g * NSPLIT + s) * TOPK + lane;
        g_pval[off] = outv; g_pidx[off] = outi;
    }
}

// ---------------------------------------------------------------------------
// Kernel 3: merge NSPLIT partial lists per GT -> global top-13, mark marks
// ---------------------------------------------------------------------------
__global__ __launch_bounds__(256) void topk_merge_kernel() {
    int g = blockIdx.x;
    int t = threadIdx.x;
    int w = t >> 5, lane = t & 31;
    const int NCAND = NSPLIT * TOPK;   // 208

    float cv = -2.f; int ci = 0x7FFFFFFF;
    if (t < NCAND) {
        cv = g_pval[(size_t)g * NCAND + t];
        ci = g_pidx[(size_t)g * NCAND + t];
    }

    __shared__ float sv[8]; __shared__ int si[8]; __shared__ int ss[8];
    __shared__ float selv0; __shared__ int seli[TOPK]; __shared__ int winner;

    for (int r = 0; r < TOPK; r++) {
        __syncthreads();
        float v = cv; int i = ci; int src = t;
        #pragma unroll
        for (int o = 16; o > 0; o >>= 1) {
            float ov = __shfl_xor_sync(0xffffffffu, v, o);
            int   oi = __shfl_xor_sync(0xffffffffu, i, o);
            int   os = __shfl_xor_sync(0xffffffffu, src, o);
            if (better(ov, oi, v, i)) { v = ov; i = oi; src = os; }
        }
        if (lane == 0) { sv[w] = v; si[w] = i; ss[w] = src; }
        __syncthreads();
        if (t < 32) {
            v = (t < 8) ? sv[t] : -3.f;
            i = (t < 8) ? si[t] : 0x7FFFFFFF;
            src = (t < 8) ? ss[t] : -1;
            #pragma unroll
            for (int o = 4; o > 0; o >>= 1) {
                float ov = __shfl_xor_sync(0xffffffffu, v, o);
                int   oi = __shfl_xor_sync(0xffffffffu, i, o);
                int   os = __shfl_xor_sync(0xffffffffu, src, o);
                if (better(ov, oi, v, i)) { v = ov; i = oi; src = os; }
            }
            if (t == 0) { if (r == 0) selv0 = v; seli[r] = i; winner = src; }
        }
        __syncthreads();
        if (t == winner) cv = -2.f;
    }
    __syncthreads();
    // keep-gate: if row max <= eps, reference drops all marks of this GT
    if (t < TOPK && selv0 > EPSV) {
        atomicAdd(&g_count[seli[t]], 1);
        atomicMin(&g_firstg[seli[t]], g);
    }
}

// ---------------------------------------------------------------------------
// Kernel 4: collect priors with count > 1 (vectorized reads)
// ---------------------------------------------------------------------------
__global__ __launch_bounds__(256) void collect_kernel(int Pp) {
    int i = blockIdx.x * 256 + threadIdx.x;
    int p0 = i * 4;
    if (p0 >= Pp) return;
    int4 c = ((const int4*)g_count)[i];
    if (p0 + 3 < Pp) {
        if (c.x > 1) g_list[atomicAdd(&g_nlist, 1)] = p0;
        if (c.y > 1) g_list[atomicAdd(&g_nlist, 1)] = p0 + 1;
        if (c.z > 1) g_list[atomicAdd(&g_nlist, 1)] = p0 + 2;
        if (c.w > 1) g_list[atomicAdd(&g_nlist, 1)] = p0 + 3;
    } else {
        for (int k = 0; k < 4 && p0 + k < Pp; k++)
            if (((const int*)&c)[k] > 1) g_list[atomicAdd(&g_nlist, 1)] = p0 + k;
    }
}

// ---------------------------------------------------------------------------
// Kernel 5: contested priors -> IoU argmax over GTs (first max wins)
// ---------------------------------------------------------------------------
__global__ __launch_bounds__(256) void resolve_kernel(const float* __restrict__ bbox_pred,
                                                      const float* __restrict__ bbox_gt,
                                                      int Ngt) {
    if ((int)blockIdx.x >= g_nlist) return;
    int p = g_list[blockIdx.x];
    int t = threadIdx.x;
    int w = t >> 5, lane = t & 31;

    float4 b = ((const float4*)bbox_pred)[p];
    float parea = fmaxf(b.z - b.x, 0.f) * fmaxf(b.w - b.y, 0.f);

    float cv = -1.f; int ci = t;
    if (t < Ngt) {
        float4 gb = ((const float4*)bbox_gt)[t];
        float iw = fminf(gb.z, b.z) - fmaxf(gb.x, b.x);
        float ih = fminf(gb.w, b.w) - fmaxf(gb.y, b.y);
        float inter = fmaxf(iw, 0.f) * fmaxf(ih, 0.f);
        float garea = fmaxf(gb.z - gb.x, 0.f) * fmaxf(gb.w - gb.y, 0.f);
        cv = inter / (garea + parea - inter + EPSV);
    }
    __shared__ float sv[8]; __shared__ int si[8];
    #pragma unroll
    for (int o = 16; o > 0; o >>= 1) {
        float ov = __shfl_xor_sync(0xffffffffu, cv, o);
        int   oi = __shfl_xor_sync(0xffffffffu, ci, o);
        if (better(ov, oi, cv, ci)) { cv = ov; ci = oi; }
    }
    if (lane == 0) { sv[w] = cv; si[w] = ci; }
    __syncthreads();
    if (t < 8) {
        cv = sv[t]; ci = si[t];
        #pragma unroll
        for (int o = 4; o > 0; o >>= 1) {
            float ov = __shfl_xor_sync(0xffu, cv, o);
            int   oi = __shfl_xor_sync(0xffu, ci, o);
            if (better(ov, oi, cv, ci)) { cv = ov; ci = oi; }
        }
        if (t == 0) g_firstg[p] = ci;
    }
}

// ---------------------------------------------------------------------------
// Kernel 6: outputs. layout: [P gt_index][P labels][P*80 one-hot][P*4 bboxes]
// ---------------------------------------------------------------------------
__global__ __launch_bounds__(256) void finalize_kernel(const float* __restrict__ bbox_gt,
                                                       const int* __restrict__ label_gt,
                                                       float* __restrict__ out,
                                                       int Pp, int Ngt) {
    __shared__ float4 gbox[MAXG];
    __shared__ int    glbl[MAXG];
    __shared__ int    s_cidx[256];
    int t = threadIdx.x;
    if (t < Ngt) { gbox[t] = ((const float4*)bbox_gt)[t]; glbl[t] = label_gt[t]; }
    __syncthreads();

    int pbase = blockIdx.x * 256;
    int p = pbase + t;
    int assigned = 0, lblout = 0;
    if (p < Pp) {
        int cnt = g_count[p];
        assigned = (cnt > 0) ? g_firstg[p] : 0;   // cnt>1 already resolved to argmax
        lblout   = (cnt > 0) ? glbl[assigned] : 0;
    }
    s_cidx[t] = (p < Pp) ? (glbl[assigned] - 1) : -1;
    __syncthreads();

    size_t o1 = (size_t)Pp;
    size_t o2 = (size_t)2 * Pp;
    size_t o3 = (size_t)2 * Pp + (size_t)NC * Pp;

    if (p < Pp) {
        out[p]      = (float)assigned;
        out[o1 + p] = (float)lblout;
        ((float4*)(out + o3))[p] = gbox[assigned];
    }
    float4* o2v = (float4*)(out + o2 + (size_t)pbase * NC);
    for (int e = t; e < 256 * NC / 4; e += 256) {
        int pl = e / (NC / 4);
        if (pbase + pl >= Pp) break;
        int c0 = (e - pl * (NC / 4)) * 4;
        int ci = s_cidx[pl];
        float4 v;
        v.x = (c0 + 0 == ci) ? 1.f : 0.f;
        v.y = (c0 + 1 == ci) ? 1.f : 0.f;
        v.z = (c0 + 2 == ci) ? 1.f : 0.f;
        v.w = (c0 + 3 == ci) ? 1.f : 0.f;
        o2v[e] = v;
    }
}

// ---------------------------------------------------------------------------
extern "C" void kernel_launch(void* const* d_in, const int* in_sizes, int n_in,
                              void* d_out, int out_size) {
    const float* cls_pred  = (const float*)d_in[0];
    const float* bbox_pred = (const float*)d_in[1];
    const int*   label_gt  = (const int*)d_in[2];
    const float* bbox_gt   = (const float*)d_in[3];
    float* out = (float*)d_out;

    int Pp  = in_sizes[1] / 4;   // 150000
    int Ngt = in_sizes[2];       // 256
    int ngrp = (Ngt + 3) / 4;    // 64

    transpose_init_kernel<<<(Pp + 31) / 32, 256>>>(cls_pred, Pp);
    topk_partial_kernel<<<NSPLIT * ngrp, TPB>>>(bbox_pred, bbox_gt, label_gt, Pp, Ngt, ngrp);
    topk_merge_kernel<<<Ngt, 256>>>();
    collect_kernel<<<(Pp / 4 + 256) / 256, 256>>>(Pp);
    resolve_kernel<<<Ngt * TOPK / 2 + 1, 256>>>(bbox_pred, bbox_gt, Ngt);
    finalize_kernel<<<(Pp + 255) / 256, 256>>>(bbox_gt, label_gt, out, Pp, Ngt);
}

// round 8
// speedup vs baseline: 2.9218x; 1.7075x over previous
#include <cuda_runtime.h>
#include <cstdint>

#define MAXP   150016
#define NC     80
#define TOPK   13
#define EPSV   1e-9f
#define NSPLIT 32
#define TILE   1024
#define MAXG   256
#define TPB    128      // topk block: 4 GTs, 1 warp each

// Scratch (__device__ globals; no allocation allowed)
__device__ float g_clsT[(size_t)NC * MAXP];            // transposed scores [class][prior]
__device__ int   g_count[MAXP];
__device__ int   g_firstg[MAXP];
__device__ float g_pval[(size_t)MAXG * NSPLIT * TOPK];
__device__ int   g_pidx[(size_t)MAXG * NSPLIT * TOPK];
__device__ int   g_list[MAXG * TOPK / 2 + 8];
__device__ int   g_nlist;

__device__ __forceinline__ bool better(float v1, int i1, float v2, int i2) {
    // total order: value desc, index asc (lax.top_k / first-max-wins tie rule)
    return (v1 > v2) || (v1 == v2 && i1 < i2);
}

// ---------------------------------------------------------------------------
// Kernel 1: transpose cls_pred [P][80] -> g_clsT [80][P]; init scratch
// ---------------------------------------------------------------------------
__global__ __launch_bounds__(256) void transpose_init_kernel(const float* __restrict__ cls, int Pp) {
    __shared__ float tile[32][NC + 1];
    int p0 = blockIdx.x * 32;
    int t = threadIdx.x;
    if (blockIdx.x == 0 && t == 0) g_nlist = 0;
    if (t < 32) {
        int p = p0 + t;
        if (p < Pp) { g_count[p] = 0; g_firstg[p] = 0x7FFFFFFF; }
    }
    for (int i = t; i < 32 * NC; i += 256) {
        int pl = i / NC, c = i - pl * NC;
        int p = p0 + pl;
        tile[pl][c] = (p < Pp) ? cls[(size_t)p * NC + c] : 0.f;
    }
    __syncthreads();
    for (int i = t; i < NC * 32; i += 256) {
        int c = i >> 5, pl = i & 31;
        int p = p0 + pl;
        if (p < Pp) g_clsT[(size_t)c * MAXP + p] = tile[pl][c];
    }
}

// ---------------------------------------------------------------------------
// Kernel 2: partial top-13 per (GT g, split s). One warp per GT.
// Warp-global top-13 kept DISTRIBUTED in registers: lane j (j<13) holds the
// rank-j entry. Filter threshold = warp's true 13th value, so insertion
// events are ~13*ln(chunk/13) ~ 77 per warp total. Scan order is ascending
// prior index, so strict '>' comparisons reproduce (val desc, idx asc).
// ---------------------------------------------------------------------------
__global__ __launch_bounds__(TPB) void topk_partial_kernel(const float* __restrict__ bbox_pred,
                                                           const float* __restrict__ bbox_gt,
                                                           const int* __restrict__ label_gt,
                                                           int Pp, int Ngt, int ngrp) {
    __shared__ float4 btile[TILE];
    const unsigned FULL = 0xffffffffu;

    int grp = blockIdx.x % ngrp;       // GT group (fast-varying: same split co-resident)
    int s   = blockIdx.x / ngrp;
    int t = threadIdx.x;
    int w = t >> 5, lane = t & 31;
    int g = grp * 4 + w;

    const float4 gb = ((const float4*)bbox_gt)[g];
    int cls = label_gt[g] - 1;
    const float* __restrict__ srow = g_clsT + (size_t)cls * MAXP;
    const float garea = fmaxf(gb.z - gb.x, 0.f) * fmaxf(gb.w - gb.y, 0.f);

    int chunk = (Pp + NSPLIT - 1) / NSPLIT;
    int lo = s * chunk;
    int hi = min(lo + chunk, Pp);

    // distributed sorted list (desc); sentinels lose to any real metric (>=0)
    float lv = -1.f; int li = 0x7FFFFFFF;
    float thr = -1.f;                   // current 13th value (uniform across warp)

    const float4* __restrict__ bp = (const float4*)bbox_pred;
    for (int base = lo; base < hi; base += TILE) {
        int n = min(TILE, hi - base);
        __syncthreads();
        for (int i = t; i < n; i += TPB) btile[i] = bp[base + i];
        __syncthreads();
        for (int kk = 0; kk < n; kk += 32) {
            int j = kk + lane;
            bool act = j < n;
            int p = base + j;
            float m = -1.f;
            if (act) {
                float4 b = btile[j];
                float iw = fminf(gb.z, b.z) - fmaxf(gb.x, b.x);
                float ih = fminf(gb.w, b.w) - fmaxf(gb.y, b.y);
                float inter = fmaxf(iw, 0.f) * fmaxf(ih, 0.f);
                float parea = fmaxf(b.z - b.x, 0.f) * fmaxf(b.w - b.y, 0.f);
                float iou = inter / (garea + parea - inter + EPSV);
                float i2 = iou * iou;
                m = srow[p] * (i2 * i2 * i2);       // score^1 * iou^6
            }
            unsigned mask = __ballot_sync(FULL, m > thr);
            while (mask) {                           // rare path (~77x per warp-chunk)
                int src = __ffs(mask) - 1; mask &= mask - 1;   // ascending lane = ascending p
                float cm = __shfl_sync(FULL, m, src);
                int   cp = __shfl_sync(FULL, p, src);
                if (cm > thr) {                      // recheck vs possibly-raised thr (uniform)
                    unsigned b = __ballot_sync(FULL, (lane < TOPK) && (cm > lv));
                    int pos = __ffs(b) - 1;          // nonzero: lane 12 qualifies
                    float pv = __shfl_up_sync(FULL, lv, 1);
                    int   pi = __shfl_up_sync(FULL, li, 1);
                    if (lane < TOPK && lane >= pos) {
                        lv = (lane == pos) ? cm : pv;
                        li = (lane == pos) ? cp : pi;
                    }
                    thr = __shfl_sync(FULL, lv, TOPK - 1);
                }
            }
        }
    }

    // lanes 0..12 hold the sorted warp top-13
    if (lane < TOPK) {
        size_t off = ((size_t)g * NSPLIT + s) * TOPK + lane;
        g_pval[off] = lv; g_pidx[off] = li;
    }
}

// ---------------------------------------------------------------------------
// Kernel 3: merge NSPLIT partial lists per GT -> global top-13; mark counts;
// append contested priors (count reaching 2) to g_list.
// ---------------------------------------------------------------------------
__global__ __launch_bounds__(512) void topk_merge_kernel() {
    int g = blockIdx.x;
    int t = threadIdx.x;
    int w = t >> 5, lane = t & 31;
    const int NCAND = NSPLIT * TOPK;   // 416

    float cv = -2.f; int ci = 0x7FFFFFFF;
    if (t < NCAND) {
        cv = g_pval[(size_t)g * NCAND + t];
        ci = g_pidx[(size_t)g * NCAND + t];
    }

    __shared__ float sv[16]; __shared__ int si[16]; __shared__ int ss[16];
    __shared__ float selv0; __shared__ int seli[TOPK]; __shared__ int winner;

    for (int r = 0; r < TOPK; r++) {
        __syncthreads();
        float v = cv; int i = ci; int src = t;
        #pragma unroll
        for (int o = 16; o > 0; o >>= 1) {
            float ov = __shfl_xor_sync(0xffffffffu, v, o);
            int   oi = __shfl_xor_sync(0xffffffffu, i, o);
            int   os = __shfl_xor_sync(0xffffffffu, src, o);
            if (better(ov, oi, v, i)) { v = ov; i = oi; src = os; }
        }
        if (lane == 0) { sv[w] = v; si[w] = i; ss[w] = src; }
        __syncthreads();
        if (t < 32) {
            v = (t < 16) ? sv[t] : -3.f;
            i = (t < 16) ? si[t] : 0x7FFFFFFF;
            src = (t < 16) ? ss[t] : -1;
            #pragma unroll
            for (int o = 8; o > 0; o >>= 1) {
                float ov = __shfl_xor_sync(0xffffffffu, v, o);
                int   oi = __shfl_xor_sync(0xffffffffu, i, o);
                int   os = __shfl_xor_sync(0xffffffffu, src, o);
                if (better(ov, oi, v, i)) { v = ov; i = oi; src = os; }
            }
            if (t == 0) { if (r == 0) selv0 = v; seli[r] = i; winner = src; }
        }
        __syncthreads();
        if (t == winner) cv = -2.f;
    }
    __syncthreads();
    // keep-gate: if row max <= eps, reference drops all marks of this GT
    if (t < TOPK && selv0 > EPSV) {
        int p = seli[t];
        int old = atomicAdd(&g_count[p], 1);
        atomicMin(&g_firstg[p], g);
        if (old == 1) g_list[atomicAdd(&g_nlist, 1)] = p;   // exactly once per contested p
    }
}

// ---------------------------------------------------------------------------
// Kernel 4: contested priors -> IoU argmax over GTs (first max wins)
// ---------------------------------------------------------------------------
__global__ __launch_bounds__(256) void resolve_kernel(const float* __restrict__ bbox_pred,
                                                      const float* __restrict__ bbox_gt,
                                                      int Ngt) {
    if ((int)blockIdx.x >= g_nlist) return;
    int p = g_list[blockIdx.x];
    int t = threadIdx.x;
    int w = t >> 5, lane = t & 31;

    float4 b = ((const float4*)bbox_pred)[p];
    float parea = fmaxf(b.z - b.x, 0.f) * fmaxf(b.w - b.y, 0.f);

    float cv = -1.f; int ci = t;
    if (t < Ngt) {
        float4 gb = ((const float4*)bbox_gt)[t];
        float iw = fminf(gb.z, b.z) - fmaxf(gb.x, b.x);
        float ih = fminf(gb.w, b.w) - fmaxf(gb.y, b.y);
        float inter = fmaxf(iw, 0.f) * fmaxf(ih, 0.f);
        float garea = fmaxf(gb.z - gb.x, 0.f) * fmaxf(gb.w - gb.y, 0.f);
        cv = inter / (garea + parea - inter + EPSV);
    }
    __shared__ float sv[8]; __shared__ int si[8];
    #pragma unroll
    for (int o = 16; o > 0; o >>= 1) {
        float ov = __shfl_xor_sync(0xffffffffu, cv, o);
        int   oi = __shfl_xor_sync(0xffffffffu, ci, o);
        if (better(ov, oi, cv, ci)) { cv = ov; ci = oi; }
    }
    if (lane == 0) { sv[w] = cv; si[w] = ci; }
    __syncthreads();
    if (t < 8) {
        cv = sv[t]; ci = si[t];
        #pragma unroll
        for (int o = 4; o > 0; o >>= 1) {
            float ov = __shfl_xor_sync(0xffu, cv, o);
            int   oi = __shfl_xor_sync(0xffu, ci, o);
            if (better(ov, oi, cv, ci)) { cv = ov; ci = oi; }
        }
        if (t == 0) g_firstg[p] = ci;
    }
}

// ---------------------------------------------------------------------------
// Kernel 5: outputs. layout: [P gt_index][P labels][P*80 one-hot][P*4 bboxes]
// ---------------------------------------------------------------------------
__global__ __launch_bounds__(256) void finalize_kernel(const float* __restrict__ bbox_gt,
                                                       const int* __restrict__ label_gt,
                                                       float* __restrict__ out,
                                                       int Pp, int Ngt) {
    __shared__ float4 gbox[MAXG];
    __shared__ int    glbl[MAXG];
    __shared__ int    s_cidx[256];
    int t = threadIdx.x;
    if (t < Ngt) { gbox[t] = ((const float4*)bbox_gt)[t]; glbl[t] = label_gt[t]; }
    __syncthreads();

    int pbase = blockIdx.x * 256;
    int p = pbase + t;
    int assigned = 0, lblout = 0;
    if (p < Pp) {
        int cnt = g_count[p];
        assigned = (cnt > 0) ? g_firstg[p] : 0;   // cnt>1 already resolved to argmax
        lblout   = (cnt > 0) ? glbl[assigned] : 0;
    }
    s_cidx[t] = (p < Pp) ? (glbl[assigned] - 1) : -1;
    __syncthreads();

    size_t o1 = (size_t)Pp;
    size_t o2 = (size_t)2 * Pp;
    size_t o3 = (size_t)2 * Pp + (size_t)NC * Pp;

    if (p < Pp) {
        out[p]      = (float)assigned;
        out[o1 + p] = (float)lblout;
        ((float4*)(out + o3))[p] = gbox[assigned];
    }
    float4* o2v = (float4*)(out + o2 + (size_t)pbase * NC);
    for (int e = t; e < 256 * NC / 4; e += 256) {
        int pl = e / (NC / 4);
        if (pbase + pl >= Pp) break;
        int c0 = (e - pl * (NC / 4)) * 4;
        int ci = s_cidx[pl];
        float4 v;
        v.x = (c0 + 0 == ci) ? 1.f : 0.f;
        v.y = (c0 + 1 == ci) ? 1.f : 0.f;
        v.z = (c0 + 2 == ci) ? 1.f : 0.f;
        v.w = (c0 + 3 == ci) ? 1.f : 0.f;
        o2v[e] = v;
    }
}

// ---------------------------------------------------------------------------
extern "C" void kernel_launch(void* const* d_in, const int* in_sizes, int n_in,
                              void* d_out, int out_size) {
    const float* cls_pred  = (const float*)d_in[0];
    const float* bbox_pred = (const float*)d_in[1];
    const int*   label_gt  = (const int*)d_in[2];
    const float* bbox_gt   = (const float*)d_in[3];
    float* out = (float*)d_out;

    int Pp  = in_sizes[1] / 4;   // 150000
    int Ngt = in_sizes[2];       // 256
    int ngrp = (Ngt + 3) / 4;    // 64

    transpose_init_kernel<<<(Pp + 31) / 32, 256>>>(cls_pred, Pp);
    topk_partial_kernel<<<NSPLIT * ngrp, TPB>>>(bbox_pred, bbox_gt, label_gt, Pp, Ngt, ngrp);
    topk_merge_kernel<<<Ngt, 512>>>();
    resolve_kernel<<<MAXG * TOPK / 2 + 1, 256>>>(bbox_pred, bbox_gt, Ngt);
    finalize_kernel<<<(Pp + 255) / 256, 256>>>(bbox_gt, label_gt, out, Pp, Ngt);
}